// round 6
// baseline (speedup 1.0000x reference)
#include <cuda_runtime.h>
#include <cstdint>
#include <math.h>

// ---------------------------------------------------------------------------
// Problem constants (fixed by the dataset)
// ---------------------------------------------------------------------------
#define Bb   512
#define Tt   50
#define Dd   100
#define BT   (Bb*Tt)          // 25600
#define NN   100000
#define NOUT (NN-1)           // 99999

typedef unsigned long long ull;

// ---------------------------------------------------------------------------
// f32x2 packed-FMA helpers (sm_100a+/sm_103a FFMA2 path)
// ---------------------------------------------------------------------------
__device__ __forceinline__ ull pack2(float x, float y) {
    ull r; asm("mov.b64 %0, {%1, %2};" : "=l"(r) : "f"(x), "f"(y)); return r;
}
__device__ __forceinline__ void unpack2(ull v, float& x, float& y) {
    asm("mov.b64 {%0, %1}, %2;" : "=f"(x), "=f"(y) : "l"(v));
}
__device__ __forceinline__ void fma2(ull& d, ull a, ull b) {
    asm("fma.rn.f32x2 %0, %1, %2, %3;" : "=l"(d) : "l"(a), "l"(b), "l"(d));
}
__device__ __forceinline__ float sigmoidf_(float x) { return 1.0f / (1.0f + expf(-x)); }

// ---------------------------------------------------------------------------
// Scratch (static device globals: runtime allocation is forbidden)
// ---------------------------------------------------------------------------
__device__ float g_h   [BT*Dd];     // gathered embeddings (h)
__device__ float g_hin [BT*Dd];     // h@W_in + b_in
__device__ float g_hout[BT*Dd];     // h@W_out + b_out
__device__ float g_X   [BT*3*Dd];   // [a_in | a_out | h]  -> later [a_in | a_out | r*h]
__device__ float g_rh  [BT*Dd];     // r * h
__device__ float g_u   [BT*Dd];     // update gate u
__device__ float g_hnew[BT*Dd];     // re_emb
__device__ float g_seqh[BT*Dd];     // seq_h (alias-gathered re_emb)
__device__ float g_seq [BT*Dd];     // seq_h @ nasr_w2
__device__ float g_last[Bb*Dd];     // last_h @ nasr_w1
__device__ float g_y1  [Bb*Dd];     // ma @ B_mat

// ---------------------------------------------------------------------------
// K1: gather h = embedding[item]; also seed g_X[:,200:300] = h
// ---------------------------------------------------------------------------
__global__ void gather_h_kernel(const float* __restrict__ emb,
                                const int* __restrict__ item) {
    int i = blockIdx.x * 256 + threadIdx.x;
    if (i >= BT*Dd) return;
    int row = i / Dd;
    int c   = i - row * Dd;
    float v = emb[(size_t)item[row] * Dd + c];
    g_h[i] = v;
    g_X[(size_t)row * 300 + 200 + c] = v;
}

// ---------------------------------------------------------------------------
// Generic tiled fp32 GEMM with f32x2 accumulators.
//   C[M,N] = epi(A[M,K] @ B + bias)
//   TRANSB=false: B is [K,N] row-major (ldb = row stride)
//   TRANSB=true : B is [N,K] row-major (ldb = row stride), i.e. C = A @ B^T
// Tile: BM=128, BN=64, BK=16; 256 threads; thread tile 8x4 (2 f32x2 col pairs).
// A is stored lane-duplicated in SMEM (ull) so the hot loop is LDS + FFMA2 only.
// EPI: 0 = plain (+bias if non-null)
//      1 = gates: v=sigmoid(v+bias); n<100 -> y1p=r*h ; n>=100 -> y2p=u
//      2 = cand : c=tanh(v+bias); C = u*h + (1-u)*c
// M must be a multiple of 128 (true for all call sites: 25600, 512).
// ---------------------------------------------------------------------------
template<int EPI, bool TRANSB>
__global__ void __launch_bounds__(256)
gemm_kernel(const float* __restrict__ A, const float* __restrict__ Bm,
            const float* __restrict__ bias, float* __restrict__ C,
            int M, int N, int K, int lda, int ldb, int ldc,
            const float* __restrict__ x1,   // EPI1/2: h
            const float* __restrict__ x2,   // EPI2:   u
            float* __restrict__ y1p,        // EPI1:   r*h out
            float* __restrict__ y2p)        // EPI1:   u out
{
    const int BM = 128, BN = 64, BK = 16;
    __shared__ ull   As2[BK][BM];   // 16 KB, value duplicated in both lanes
    __shared__ float Bs [BK][BN];   // 4 KB

    int tid = threadIdx.x;
    int tx  = tid & 15;             // N direction (16 * 4 cols)
    int ty  = tid >> 4;             // M direction (16 * 8 rows)
    int m0  = blockIdx.y * BM;
    int n0  = blockIdx.x * BN;

    // loader indices
    int alr = tid >> 1;             // 0..127 : A row
    int alk = (tid & 1) * 8;        // 0 or 8 : A k-offset
    int blk = tid >> 4;             // 0..15  : B k (non-trans)
    int bln = (tid & 15) * 4;       //        : B n (non-trans)
    int bnt = tid >> 2;             // 0..63  : B n (trans)
    int bkt = (tid & 3) * 4;        //        : B k (trans)

    ull acc[8][2];
    #pragma unroll
    for (int i = 0; i < 8; i++) { acc[i][0] = 0ULL; acc[i][1] = 0ULL; }

    for (int k0 = 0; k0 < K; k0 += BK) {
        // --- load A tile (transposed + lane-duplicated) ---
        const float* Arow = A + (size_t)(m0 + alr) * lda;
        #pragma unroll
        for (int j = 0; j < 8; j++) {
            int k = k0 + alk + j;
            float v = (k < K) ? Arow[k] : 0.0f;
            As2[alk + j][alr] = pack2(v, v);
        }
        // --- load B tile ---
        if (!TRANSB) {
            #pragma unroll
            for (int j = 0; j < 4; j++) {
                int k = k0 + blk, n = n0 + bln + j;
                Bs[blk][bln + j] = (k < K && n < N) ? Bm[(size_t)k * ldb + n] : 0.0f;
            }
        } else {
            const float* Brow = Bm + (size_t)(n0 + bnt) * ldb;
            bool nok = (n0 + bnt) < N;
            #pragma unroll
            for (int j = 0; j < 4; j++) {
                int k = k0 + bkt + j;
                Bs[bkt + j][bnt] = (nok && k < K) ? Brow[k] : 0.0f;
            }
        }
        __syncthreads();

        #pragma unroll
        for (int kk = 0; kk < BK; kk++) {
            const ull* bp = reinterpret_cast<const ull*>(&Bs[kk][tx * 4]);
            ull b0 = bp[0], b1 = bp[1];
            const ulonglong2* ap = reinterpret_cast<const ulonglong2*>(&As2[kk][ty * 8]);
            ulonglong2 a01 = ap[0], a23 = ap[1], a45 = ap[2], a67 = ap[3];
            ull av[8] = {a01.x, a01.y, a23.x, a23.y, a45.x, a45.y, a67.x, a67.y};
            #pragma unroll
            for (int i = 0; i < 8; i++) {
                fma2(acc[i][0], av[i], b0);
                fma2(acc[i][1], av[i], b1);
            }
        }
        __syncthreads();
    }

    // --- epilogue ---
    #pragma unroll
    for (int i = 0; i < 8; i++) {
        int gm = m0 + ty * 8 + i;
        if (gm >= M) continue;
        #pragma unroll
        for (int p = 0; p < 2; p++) {
            float v0, v1;
            unpack2(acc[i][p], v0, v1);
            int gn0 = n0 + tx * 4 + p * 2;
            float vs[2] = {v0, v1};
            #pragma unroll
            for (int q = 0; q < 2; q++) {
                int gn = gn0 + q;
                if (gn >= N) continue;
                float v = vs[q];
                if (EPI == 0) {
                    if (bias) v += bias[gn];
                    C[(size_t)gm * ldc + gn] = v;
                } else if (EPI == 1) {
                    float g = sigmoidf_(v + bias[gn]);
                    if (gn < Dd) {
                        y1p[(size_t)gm * Dd + gn] = g * x1[(size_t)gm * Dd + gn];
                    } else {
                        y2p[(size_t)gm * Dd + (gn - Dd)] = g;
                    }
                } else { // EPI == 2
                    float cc = tanhf(v + bias[gn]);
                    float uu = x2[(size_t)gm * Dd + gn];
                    float hh = x1[(size_t)gm * Dd + gn];
                    C[(size_t)gm * ldc + gn] = uu * hh + (1.0f - uu) * cc;
                }
            }
        }
    }
}

// ---------------------------------------------------------------------------
// K3: per-batch adjacency propagation  a[t,c] = sum_s adj[b,t,s] * hv[b,s,c]
// One block per batch; writes into g_X at column offset coloff.
// 2x4 register tile via f32x2.
// ---------------------------------------------------------------------------
__global__ void __launch_bounds__(256)
adj_kernel(const float* __restrict__ adj, const float* __restrict__ hv, int coloff)
{
    __shared__ float adjS[Tt*Tt];   // 10 KB
    __shared__ float hS[Tt*Dd];     // 20 KB
    int b = blockIdx.x;
    int tid = threadIdx.x;
    for (int i = tid; i < Tt*Tt; i += 256) adjS[i] = adj[(size_t)b*Tt*Tt + i];
    for (int i = tid; i < Tt*Dd; i += 256) hS[i]   = hv[(size_t)b*Tt*Dd + i];
    __syncthreads();

    // tasks: 25 t-pairs x 25 col-quads = 625
    for (int task = tid; task < 625; task += 256) {
        int tg = task / 25, cg = task - tg * 25;
        int t0 = tg * 2, c0 = cg * 4;
        ull a00 = 0, a01 = 0, a10 = 0, a11 = 0;
        #pragma unroll 5
        for (int s = 0; s < Tt; s++) {
            const ull* hp = reinterpret_cast<const ull*>(&hS[s * Dd + c0]);
            ull b0 = hp[0], b1 = hp[1];
            float w0 = adjS[t0 * Tt + s];
            float w1 = adjS[(t0 + 1) * Tt + s];
            ull p0 = pack2(w0, w0), p1 = pack2(w1, w1);
            fma2(a00, p0, b0); fma2(a01, p0, b1);
            fma2(a10, p1, b0); fma2(a11, p1, b1);
        }
        float o0, o1, o2, o3;
        size_t base0 = (size_t)(b * Tt + t0) * 300 + coloff + c0;
        unpack2(a00, o0, o1); unpack2(a01, o2, o3);
        g_X[base0 + 0] = o0; g_X[base0 + 1] = o1; g_X[base0 + 2] = o2; g_X[base0 + 3] = o3;
        size_t base1 = (size_t)(b * Tt + t0 + 1) * 300 + coloff + c0;
        unpack2(a10, o0, o1); unpack2(a11, o2, o3);
        g_X[base1 + 0] = o0; g_X[base1 + 1] = o1; g_X[base1 + 2] = o2; g_X[base1 + 3] = o3;
    }
}

// ---------------------------------------------------------------------------
// K5: splice r*h into g_X[:,200:300]
// ---------------------------------------------------------------------------
__global__ void splice_rh_kernel() {
    int i = blockIdx.x * 256 + threadIdx.x;
    if (i >= BT*Dd) return;
    int row = i / Dd;
    int c   = i - row * Dd;
    g_X[(size_t)row * 300 + 200 + c] = g_rh[i];
}

// ---------------------------------------------------------------------------
// K7a: per-batch last vector: rm=sum(mask); last_h=re_emb[b, alias[b,rm-1]];
//      g_last[b] = last_h @ nasr_w1
// ---------------------------------------------------------------------------
__global__ void last_kernel(const float* __restrict__ mask,
                            const int* __restrict__ alias_,
                            const float* __restrict__ w1)
{
    __shared__ float msum[Tt];
    __shared__ float lh[Dd];
    __shared__ int   liS;
    int b = blockIdx.x;
    int tid = threadIdx.x;
    if (tid < Tt) msum[tid] = mask[b * Tt + tid];
    __syncthreads();
    if (tid == 0) {
        float s = 0.0f;
        for (int t = 0; t < Tt; t++) s += msum[t];
        int rm = (int)s;
        liS = alias_[b * Tt + (rm - 1)];
    }
    __syncthreads();
    int li = liS;
    if (tid < Dd) lh[tid] = g_hnew[(size_t)(b * Tt + li) * Dd + tid];
    __syncthreads();
    if (tid < Dd) {
        float acc = 0.0f;
        #pragma unroll 4
        for (int k = 0; k < Dd; k++) acc += lh[k] * w1[k * Dd + tid];
        g_last[b * Dd + tid] = acc;
    }
}

// ---------------------------------------------------------------------------
// K7b: seq_h gather: g_seqh[b,t] = g_hnew[b, alias[b,t]]
// ---------------------------------------------------------------------------
__global__ void seqh_kernel(const int* __restrict__ alias_) {
    int i = blockIdx.x * 256 + threadIdx.x;
    if (i >= BT*Dd) return;
    int row = i / Dd;
    int c   = i - row * Dd;
    int b   = row / Tt;
    int al  = alias_[row];
    g_seqh[i] = g_hnew[(size_t)(b * Tt + al) * Dd + c];
}

// ---------------------------------------------------------------------------
// K9: per-batch attention + readout:
//   m = sigmoid(last + seq + nasr_b); coef = (m.v) * mask
//   ma = [sum_t coef*seq_h , last];  y1 = ma @ B_mat
// Warp-specialized over t (4 warps, shfl reductions, no per-t block syncs).
// ---------------------------------------------------------------------------
__global__ void __launch_bounds__(128)
att_kernel(const float* __restrict__ mask,
           const float* __restrict__ vv,     // nasr_v (100)
           const float* __restrict__ nb,     // nasr_b (100)
           const float* __restrict__ Bmat)   // (200,100)
{
    __shared__ float lastS[Dd], nbS[Dd], vS[Dd];
    __shared__ float acc4[4][Dd];
    __shared__ float maS[2 * Dd];
    int b = blockIdx.x;
    int tid = threadIdx.x;
    int w = tid >> 5, lane = tid & 31;

    if (tid < Dd) { lastS[tid] = g_last[b * Dd + tid]; nbS[tid] = nb[tid]; vS[tid] = vv[tid]; }
    __syncthreads();

    float accR[4] = {0.f, 0.f, 0.f, 0.f};
    for (int t = w; t < Tt; t += 4) {
        const float* seqrow = &g_seq [(size_t)(b * Tt + t) * Dd];
        const float* shrow  = &g_seqh[(size_t)(b * Tt + t) * Dd];
        float part = 0.0f;
        #pragma unroll
        for (int j = 0; j < 4; j++) {
            int c = lane + 32 * j;
            if (c < Dd) {
                float m = sigmoidf_(lastS[c] + seqrow[c] + nbS[c]);
                part += m * vS[c];
            }
        }
        #pragma unroll
        for (int off = 16; off > 0; off >>= 1)
            part += __shfl_xor_sync(0xffffffffu, part, off);
        float coef = part * mask[b * Tt + t];
        #pragma unroll
        for (int j = 0; j < 4; j++) {
            int c = lane + 32 * j;
            if (c < Dd) accR[j] += coef * shrow[c];
        }
    }
    #pragma unroll
    for (int j = 0; j < 4; j++) {
        int c = lane + 32 * j;
        if (c < Dd) acc4[w][c] = accR[j];
    }
    __syncthreads();
    if (tid < Dd) {
        maS[tid]      = acc4[0][tid] + acc4[1][tid] + acc4[2][tid] + acc4[3][tid];
        maS[Dd + tid] = lastS[tid];
    }
    __syncthreads();
    if (tid < Dd) {
        float y = 0.0f;
        #pragma unroll 4
        for (int k = 0; k < 2 * Dd; k++) y += maS[k] * Bmat[k * Dd + tid];
        g_y1[b * Dd + tid] = y;
    }
}

// ---------------------------------------------------------------------------
// Host launcher
// ---------------------------------------------------------------------------
static inline int cdiv(int a, int b) { return (a + b - 1) / b; }

extern "C" void kernel_launch(void* const* d_in, const int* in_sizes, int n_in,
                              void* d_out, int out_size)
{
    // Input order per metadata: adj_in, adj_out, mask, item, alias, step,
    // embedding, W_in, b_in, W_out, b_out, gru_gate_k, gru_gate_b,
    // gru_cand_k, gru_cand_b, nasr_w1, nasr_w2, nasr_v, nasr_b, B_mat.
    // Guard against the scalar `step` being omitted from the input list.
    int o = 0;
    if (n_in < 20 || in_sizes[5] != 1) o = -1;  // step missing -> shift tail down

    const float* adj_in  = (const float*)d_in[0];
    const float* adj_out = (const float*)d_in[1];
    const float* mask    = (const float*)d_in[2];
    const int*   item    = (const int*)  d_in[3];
    const int*   alias_  = (const int*)  d_in[4];
    const float* emb     = (const float*)d_in[6  + o];
    const float* W_in    = (const float*)d_in[7  + o];
    const float* b_in    = (const float*)d_in[8  + o];
    const float* W_out   = (const float*)d_in[9  + o];
    const float* b_out   = (const float*)d_in[10 + o];
    const float* ggk     = (const float*)d_in[11 + o];
    const float* ggb     = (const float*)d_in[12 + o];
    const float* gck     = (const float*)d_in[13 + o];
    const float* gcb     = (const float*)d_in[14 + o];
    const float* w1      = (const float*)d_in[15 + o];
    const float* w2      = (const float*)d_in[16 + o];
    const float* vv      = (const float*)d_in[17 + o];
    const float* nb      = (const float*)d_in[18 + o];
    const float* Bmat    = (const float*)d_in[19 + o];
    float* out = (float*)d_out;

    // Resolve scratch symbol addresses (host API, not stream-ordered: capture-safe)
    void *p;
    cudaGetSymbolAddress(&p, g_h);    float* ph    = (float*)p;
    cudaGetSymbolAddress(&p, g_hin);  float* phin  = (float*)p;
    cudaGetSymbolAddress(&p, g_hout); float* phout = (float*)p;
    cudaGetSymbolAddress(&p, g_X);    float* pX    = (float*)p;
    cudaGetSymbolAddress(&p, g_rh);   float* prh   = (float*)p;
    cudaGetSymbolAddress(&p, g_u);    float* pu    = (float*)p;
    cudaGetSymbolAddress(&p, g_hnew); float* phnew = (float*)p;
    cudaGetSymbolAddress(&p, g_seqh); float* pseqh = (float*)p;
    cudaGetSymbolAddress(&p, g_seq);  float* pseq  = (float*)p;
    cudaGetSymbolAddress(&p, g_y1);   float* py1   = (float*)p;

    const int EW = cdiv(BT * Dd, 256);   // elementwise grid (10000 blocks)

    // ---- GGNN (step = 1 in this dataset) ----
    gather_h_kernel<<<EW, 256>>>(emb, item);

    gemm_kernel<0, false><<<dim3(cdiv(Dd, 64), cdiv(BT, 128)), 256>>>(
        ph, W_in, b_in, phin, BT, Dd, Dd, Dd, Dd, Dd,
        nullptr, nullptr, nullptr, nullptr);
    gemm_kernel<0, false><<<dim3(cdiv(Dd, 64), cdiv(BT, 128)), 256>>>(
        ph, W_out, b_out, phout, BT, Dd, Dd, Dd, Dd, Dd,
        nullptr, nullptr, nullptr, nullptr);

    adj_kernel<<<Bb, 256>>>(adj_in,  phin,  0);
    adj_kernel<<<Bb, 256>>>(adj_out, phout, Dd);

    // gates = sigmoid(X @ ggk + ggb); r*h -> g_rh, u -> g_u
    gemm_kernel<1, false><<<dim3(cdiv(2 * Dd, 64), cdiv(BT, 128)), 256>>>(
        pX, ggk, ggb, nullptr, BT, 2 * Dd, 3 * Dd, 3 * Dd, 2 * Dd, 0,
        ph, nullptr, prh, pu);

    splice_rh_kernel<<<EW, 256>>>();

    // c = tanh(X' @ gck + gcb); h_new = u*h + (1-u)*c
    gemm_kernel<2, false><<<dim3(cdiv(Dd, 64), cdiv(BT, 128)), 256>>>(
        pX, gck, gcb, phnew, BT, Dd, 3 * Dd, 3 * Dd, Dd, Dd,
        ph, pu, nullptr, nullptr);

    // ---- attention readout ----
    last_kernel<<<Bb, 128>>>(mask, alias_, w1);
    seqh_kernel<<<EW, 256>>>(alias_);

    gemm_kernel<0, false><<<dim3(cdiv(Dd, 64), cdiv(BT, 128)), 256>>>(
        pseqh, w2, nullptr, pseq, BT, Dd, Dd, Dd, Dd, Dd,
        nullptr, nullptr, nullptr, nullptr);

    att_kernel<<<Bb, 128>>>(mask, vv, nb, Bmat);

    // ---- logits = y1 @ embedding[1:]^T  (512 x 99999 x 100) ----
    gemm_kernel<0, true><<<dim3(cdiv(NOUT, 64), cdiv(Bb, 128)), 256>>>(
        py1, emb + Dd, nullptr, out, Bb, NOUT, Dd, Dd, Dd, NOUT,
        nullptr, nullptr, nullptr, nullptr);
}